// round 15
// baseline (speedup 1.0000x reference)
#include <cuda_runtime.h>
#include <cuda_bf16.h>
#include <cstdint>

#define BATCH 4
#define SEQ   2048
#define DM    1024
#define NH    16
#define HD    64
#define MR    (BATCH*SEQ)   // 8192

// ---------------------------------------------------------------------------
// Scratch (__device__ globals: allocation-free rule)
// ---------------------------------------------------------------------------
__device__ __align__(128) __nv_bfloat16 g_Xc[3][(size_t)MR * 2048];     // q,k,v inputs [MR, hi|lo]
__device__ __align__(128) __nv_bfloat16 g_Wct[4][(size_t)1024 * 2048];  // Wq,Wk,Wv,Wo [n, hi|lo over k]
__device__ __align__(128) __nv_bfloat16 g_Qc[(size_t)64 * SEQ * 128];   // [bh, s, hi(64)|lo(64)] (scaled by log2e/8)
__device__ __align__(128) __nv_bfloat16 g_Kc[(size_t)64 * SEQ * 128];
__device__ __align__(128) __nv_bfloat16 g_Vt[(size_t)64 * 2 * HD * SEQ];// [bh, {hi,lo}, d, s]
__device__ __align__(128) __nv_bfloat16 g_Zc[(size_t)MR * 2048];        // [MR, hi|lo]

// ---------------------------------------------------------------------------
// Helpers
// ---------------------------------------------------------------------------
__device__ __forceinline__ uint32_t smem_u32(const void* p) {
    uint32_t a;
    asm("{ .reg .u64 t; cvta.to.shared.u64 t, %1; cvt.u32.u64 %0, t; }" : "=r"(a) : "l"(p));
    return a;
}
#define SWZ(o) ((o) ^ (((o) >> 3) & 0x70))
#define CP16(dst, src) asm volatile("cp.async.cg.shared.global [%0], [%1], 16;" :: "r"(dst), "l"(src))
#define CP_COMMIT() asm volatile("cp.async.commit_group;" ::: "memory")
#define CP_WAIT0()  asm volatile("cp.async.wait_group 0;" ::: "memory")
#define CP_WAIT1()  asm volatile("cp.async.wait_group 1;" ::: "memory")

#define LDMX4(r, addr) asm volatile( \
    "ldmatrix.sync.aligned.m8n8.x4.shared.b16 {%0,%1,%2,%3}, [%4];" \
    : "=r"((r)[0]), "=r"((r)[1]), "=r"((r)[2]), "=r"((r)[3]) : "r"(addr))

#define MMA16816(c, a, b0, b1) asm volatile( \
    "mma.sync.aligned.m16n8k16.row.col.f32.bf16.bf16.f32 " \
    "{%0,%1,%2,%3},{%4,%5,%6,%7},{%8,%9},{%0,%1,%2,%3};" \
    : "+f"((c)[0]), "+f"((c)[1]), "+f"((c)[2]), "+f"((c)[3]) \
    : "r"((a)[0]), "r"((a)[1]), "r"((a)[2]), "r"((a)[3]), "r"(b0), "r"(b1))

#define EX2(d, x) asm("ex2.approx.f32 %0, %1;" : "=f"(d) : "f"(x))

__device__ __forceinline__ void hilo(float v, __nv_bfloat16& h, __nv_bfloat16& l) {
    h = __float2bfloat16(v);
    l = __float2bfloat16(v - __bfloat162float(h));
}
__device__ __forceinline__ uint32_t pack2(float x, float y) {
    __nv_bfloat162 t = __floats2bfloat162_rn(x, y);
    return *(uint32_t*)&t;
}

// ---------------------------------------------------------------------------
// Converters
// ---------------------------------------------------------------------------
__global__ void conv_x3(const float* __restrict__ X0, const float* __restrict__ X1,
                        const float* __restrict__ X2) {
    const float* X = blockIdx.y == 0 ? X0 : (blockIdx.y == 1 ? X1 : X2);
    __nv_bfloat16* Xc = g_Xc[blockIdx.y];
    int i = blockIdx.x * 256 + threadIdx.x;
    float4 v = ((const float4*)X)[i];
    int row = i >> 8;
    int c = (i & 255) * 4;
    __nv_bfloat16 h, l;
    size_t b = (size_t)row * 2048 + c;
    hilo(v.x, h, l); Xc[b + 0] = h; Xc[b + 1024 + 0] = l;
    hilo(v.y, h, l); Xc[b + 1] = h; Xc[b + 1024 + 1] = l;
    hilo(v.z, h, l); Xc[b + 2] = h; Xc[b + 1024 + 2] = l;
    hilo(v.w, h, l); Xc[b + 3] = h; Xc[b + 1024 + 3] = l;
}
__global__ void conv_w4(const float* __restrict__ W0, const float* __restrict__ W1,
                        const float* __restrict__ W2, const float* __restrict__ W3) {
    const float* W = blockIdx.z == 0 ? W0 : (blockIdx.z == 1 ? W1 :
                     (blockIdx.z == 2 ? W2 : W3));
    __nv_bfloat16* Wct = g_Wct[blockIdx.z];
    __shared__ float t[32][33];
    int bx = blockIdx.x * 32, by = blockIdx.y * 32;  // bx: k, by: n
    int x = threadIdx.x & 31, y = threadIdx.x >> 5;
    #pragma unroll
    for (int i = 0; i < 32; i += 8) t[y + i][x] = W[(size_t)(bx + y + i) * 1024 + by + x];
    __syncthreads();
    #pragma unroll
    for (int i = 0; i < 32; i += 8) {
        float v = t[x][y + i];                        // W[bx+x, by+y+i]
        __nv_bfloat16 h, l; hilo(v, h, l);
        size_t n = by + y + i, k = bx + x;
        Wct[n * 2048 + k] = h;
        Wct[n * 2048 + 1024 + k] = l;
    }
}

// ---------------------------------------------------------------------------
// mma.sync GEMM, CTA tile 64x128, FOUR warps (each 32x64, 2x2 grid), BK=64,
// 3-stage cp.async pipeline, one barrier per chunk, ping-pong fragments.
// 3 CTAs/SM. A cat=[hi|lo|hi] (3072), B cat=[hi|hi|lo].
// MODE 3: merged QKV (z selects input/weight/bias; Q scaled by log2e/8).
// MODE 2: fp32 out.
// ---------------------------------------------------------------------------
#define GSMEM (3 * 24576 + 1024)

template <int MODE>
__global__ void __launch_bounds__(128, 3)
gemm_big(const float* __restrict__ bias0, const float* __restrict__ bias1,
         const float* __restrict__ bias2, void* __restrict__ Cout)
{
    extern __shared__ char dsm[];
    const uint32_t sb = (smem_u32(dsm) + 1023u) & ~1023u;
    const int tid = threadIdx.x, w = tid >> 5, lane = tid & 31;
    const int wm = w >> 1, wn = w & 1;               // 2 x 2 warp grid
    const int m0 = blockIdx.y * 64, n0 = blockIdx.x * 128;
    const int z = (MODE == 3) ? blockIdx.z : 3;

    const __nv_bfloat16* A = (MODE == 3) ? g_Xc[z] : g_Zc;
    const __nv_bfloat16* Bw = g_Wct[z];
    const float* bias = (MODE == 3) ? (z == 0 ? bias0 : (z == 1 ? bias1 : bias2))
                                    : bias0;

    auto load_chunk = [&](int c, int buf) {
        int kk = c * 64;
        int ka = kk < 2048 ? kk : kk - 2048;        // A: [hi|lo|hi]
        int kb = kk < 1024 ? kk : kk - 1024;        // B: [hi|hi|lo]
        uint32_t ab = sb + buf * 24576, bb = ab + 8192;
        #pragma unroll
        for (int i = 0; i < 4; i++) {               // A: 64 rows x 8 slots
            int u = tid + i * 128, row = u >> 3, sl = u & 7;
            CP16(ab + SWZ(row * 128 + sl * 16), A + (size_t)(m0 + row) * 2048 + ka + sl * 8);
        }
        #pragma unroll
        for (int i = 0; i < 8; i++) {               // B: 128 rows x 8 slots
            int u = tid + i * 128, row = u >> 3, sl = u & 7;
            CP16(bb + SWZ(row * 128 + sl * 16), Bw + (size_t)(n0 + row) * 2048 + kb + sl * 8);
        }
    };

    float acc[2][8][4];
    #pragma unroll
    for (int mt = 0; mt < 2; mt++)
        #pragma unroll
        for (int nt = 0; nt < 8; nt++)
            #pragma unroll
            for (int r = 0; r < 4; r++) acc[mt][nt][r] = 0.f;

    const int NC = 48;
    load_chunk(0, 0); CP_COMMIT();
    load_chunk(1, 1); CP_COMMIT();
    for (int c = 0; c < NC; c++) {
        if (c + 1 < NC) CP_WAIT1(); else CP_WAIT0();
        __syncthreads();     // also: compute(c-1) done -> buffer (c+2)%3 free
        if (c + 2 < NC) { load_chunk(c + 2, (c + 2) % 3); CP_COMMIT(); }

        const uint32_t ab = sb + (c % 3) * 24576, bb = ab + 8192;
        uint32_t a[2][2][4], b[2][4];
        auto lda = [&](uint32_t (&d)[2][4], int kkv) {
            #pragma unroll
            for (int mt = 0; mt < 2; mt++)
                LDMX4(d[mt], ab + SWZ((wm * 32 + mt * 16 + (lane & 15)) * 128
                                      + kkv * 32 + (lane >> 4) * 16));
        };
        auto ldb = [&](uint32_t (&d)[4], int kkv, int pv) {
            LDMX4(d, bb + SWZ((wn * 64 + pv * 16 + ((lane >> 4) << 3) + (lane & 7)) * 128
                              + kkv * 32 + ((lane >> 3) & 1) * 16));
        };
        lda(a[0], 0); ldb(b[0], 0, 0);
        #pragma unroll
        for (int kk = 0; kk < 4; kk++) {
            #pragma unroll
            for (int p = 0; p < 4; p++) {
                const int cur = (kk * 4 + p) & 1;
                if (p < 3)       ldb(b[cur ^ 1], kk, p + 1);
                else if (kk < 3) { lda(a[(kk + 1) & 1], kk + 1); ldb(b[cur ^ 1], kk + 1, 0); }
                #pragma unroll
                for (int mt = 0; mt < 2; mt++) {
                    MMA16816(acc[mt][2 * p],     a[kk & 1][mt], b[cur][0], b[cur][1]);
                    MMA16816(acc[mt][2 * p + 1], a[kk & 1][mt], b[cur][2], b[cur][3]);
                }
            }
        }
    }

    // epilogue
    #pragma unroll
    for (int mt = 0; mt < 2; mt++)
        #pragma unroll
        for (int nt = 0; nt < 8; nt++)
            #pragma unroll
            for (int r = 0; r < 4; r++) {
                int row = m0 + wm * 32 + mt * 16 + (lane >> 2) + (r >> 1) * 8;
                int col = n0 + wn * 64 + nt * 8 + (lane & 3) * 2 + (r & 1);
                float val = acc[mt][nt][r] + bias[col];
                if (MODE == 2) {
                    ((float*)Cout)[(size_t)row * 1024 + col] = val;
                } else {
                    if (z == 0) val *= 0.1803368801111f;  // (1/8)*log2(e)
                    __nv_bfloat16 h, l; hilo(val, h, l);
                    int bh = (row >> 11) * 16 + (col >> 6), s = row & 2047, d = col & 63;
                    if (z < 2) {
                        __nv_bfloat16* C = z == 0 ? g_Qc : g_Kc;
                        size_t o = ((size_t)bh * 2048 + s) * 128 + d;
                        C[o] = h; C[o + 64] = l;
                    } else {
                        g_Vt[((size_t)(bh * 2 + 0) * 64 + d) * 2048 + s] = h;
                        g_Vt[((size_t)(bh * 2 + 1) * 64 + d) * 2048 + s] = l;
                    }
                }
            }
}

// ---------------------------------------------------------------------------
// Flash attention v3: CTA = (qb, bh) = 64 q-rows, TWO warps of 32 q-rows,
// 32-key double-buffered blocks, 4 CTAs/SM (fine-grained CTAs cut the wave-
// quantization tail from ~13% to ~2% and give 4 phase-desynced CTAs/SM).
// Warp tile unchanged (32 rows -> halved LDS per MMA); MUFU ex2 softmax.
// smem: Q 16K | buf0 (K 8K + V 8K) | buf1 (16K) = 48.5KB
// ---------------------------------------------------------------------------
#define ATTN_SMEM (1024 + 16384 + 2 * 16384)

__global__ void __launch_bounds__(64, 4)
attn_mma(const __nv_bfloat16* __restrict__ Qc, const __nv_bfloat16* __restrict__ Kc,
         const __nv_bfloat16* __restrict__ Vt, __nv_bfloat16* __restrict__ Zc)
{
    extern __shared__ char dsm[];
    const uint32_t sb = (smem_u32(dsm) + 1023u) & ~1023u;
    const uint32_t Qs = sb;                        // 16KB
    const int tid = threadIdx.x, w = tid >> 5, lane = tid & 31;
    const int qb = blockIdx.x, bh = blockIdx.y;

    auto load_kv = [&](int kb, uint32_t buf) {
        const uint32_t Ks = buf, Vs = buf + 8192;
        const size_t kbase = ((size_t)bh * 2048 + kb * 32) * 128;
        #pragma unroll
        for (int i = 0; i < 8; i++) {           // K: 32 keys x 256B (hi|lo rows)
            int u = tid + i * 64, key = u >> 4, seg = u & 15;
            CP16(Ks + SWZ((key * 2 + (seg >> 3)) * 128 + (seg & 7) * 16),
                 Kc + kbase + (size_t)key * 128 + seg * 8);
        }
        #pragma unroll
        for (int i = 0; i < 8; i++) {           // V: 2 parts x 64 d x 64B
            int u = tid + i * 64, part = u >> 8, v = u & 255;
            int d = v >> 2, sl = v & 3;
            CP16(Vs + part * 4096 + SWZ((d >> 1) * 128 + (d & 1) * 64 + sl * 16),
                 Vt + ((size_t)(bh * 2 + part) * 64 + d) * 2048 + kb * 32 + sl * 8);
        }
    };

    // ---- preamble: Q (64 rows x 256B) + first K/V block in flight ----
    {
        const size_t qbase = ((size_t)bh * 2048 + qb * 64) * 128;
        #pragma unroll
        for (int i = 0; i < 16; i++) {
            int u = tid + i * 64, row = u >> 4, seg = u & 15;
            CP16(Qs + SWZ((row * 2 + (seg >> 3)) * 128 + (seg & 7) * 16),
                 Qc + qbase + (size_t)row * 128 + seg * 8);
        }
        CP_COMMIT();
    }
    load_kv(0, sb + 16384); CP_COMMIT();
    CP_WAIT1();
    __syncthreads();

    // ---- Q A-fragments: 2 m16 x (4 k16 hi + 4 k16 lo), resident (64 regs) ----
    uint32_t aQ[2][8][4];
    #pragma unroll
    for (int mt = 0; mt < 2; mt++)
        #pragma unroll
        for (int t = 0; t < 8; t++)
            LDMX4(aQ[mt][t],
                  Qs + SWZ(((w * 32 + mt * 16 + (lane & 15)) * 2 + (t >> 2)) * 128
                           + (t & 3) * 32 + (lane >> 4) * 16));

    float lrow[2][2] = {{0.f, 0.f}, {0.f, 0.f}};
    float o[2][8][4];
    #pragma unroll
    for (int mt = 0; mt < 2; mt++)
        #pragma unroll
        for (int nt = 0; nt < 8; nt++)
            #pragma unroll
            for (int r = 0; r < 4; r++) o[mt][nt][r] = 0.f;

    const uint32_t ksel = ((lane >> 3) & 1) * 16;
    const uint32_t krsel = ((lane >> 4) << 3) + (lane & 7);

    for (int kb = 0; kb < 64; kb++) {
        __syncthreads();
        if (kb + 1 < 64) { load_kv(kb + 1, sb + 16384 + ((kb + 1) & 1) * 16384);
                           CP_COMMIT(); CP_WAIT1(); }
        else CP_WAIT0();
        __syncthreads();
        const uint32_t Ks = sb + 16384 + (kb & 1) * 16384, Vs = Ks + 8192;

        // ---- scores: 32 rows x 32 keys, K'=192 ----
        float s[2][4][4];
        #pragma unroll
        for (int mt = 0; mt < 2; mt++)
            #pragma unroll
            for (int nt = 0; nt < 4; nt++)
                #pragma unroll
                for (int r = 0; r < 4; r++) s[mt][nt][r] = 0.f;

        #pragma unroll
        for (int kb4 = 0; kb4 < 4; kb4++) {
            const uint32_t kbyte = kb4 * 32 + ksel;
            uint32_t bh0[4], bh1[4], bl0[4], bl1[4];
            LDMX4(bh0, Ks + SWZ((krsel * 2) * 128 + kbyte));              // K hi, keys 0-15
            LDMX4(bh1, Ks + SWZ(((16 + krsel) * 2) * 128 + kbyte));       // K hi, keys 16-31
            LDMX4(bl0, Ks + SWZ((krsel * 2 + 1) * 128 + kbyte));          // K lo, keys 0-15
            LDMX4(bl1, Ks + SWZ(((16 + krsel) * 2 + 1) * 128 + kbyte));   // K lo, keys 16-31
            #pragma unroll
            for (int mt = 0; mt < 2; mt++) {
                const uint32_t* qh = aQ[mt][kb4];
                const uint32_t* ql = aQ[mt][kb4 + 4];
                MMA16816(s[mt][0], qh, bh0[0], bh0[1]);   // Qhi·Khi
                MMA16816(s[mt][1], qh, bh0[2], bh0[3]);
                MMA16816(s[mt][2], qh, bh1[0], bh1[1]);
                MMA16816(s[mt][3], qh, bh1[2], bh1[3]);
                MMA16816(s[mt][0], ql, bh0[0], bh0[1]);   // Qlo·Khi
                MMA16816(s[mt][1], ql, bh0[2], bh0[3]);
                MMA16816(s[mt][2], ql, bh1[0], bh1[1]);
                MMA16816(s[mt][3], ql, bh1[2], bh1[3]);
                MMA16816(s[mt][0], qh, bl0[0], bl0[1]);   // Qhi·Klo
                MMA16816(s[mt][1], qh, bl0[2], bl0[3]);
                MMA16816(s[mt][2], qh, bl1[0], bl1[1]);
                MMA16816(s[mt][3], qh, bl1[2], bl1[3]);
            }
        }

        // ---- P = 2^s (MUFU ex2; log2-domain scores) + row sums ----
        float sum[2][2] = {{0.f, 0.f}, {0.f, 0.f}};
        #pragma unroll
        for (int mt = 0; mt < 2; mt++)
            #pragma unroll
            for (int nt = 0; nt < 4; nt++) {
                EX2(s[mt][nt][0], s[mt][nt][0]);
                EX2(s[mt][nt][1], s[mt][nt][1]);
                sum[mt][0] += s[mt][nt][0] + s[mt][nt][1];
                EX2(s[mt][nt][2], s[mt][nt][2]);
                EX2(s[mt][nt][3], s[mt][nt][3]);
                sum[mt][1] += s[mt][nt][2] + s[mt][nt][3];
            }

        // ---- PV: O[32,64] += [Phi|Plo]·Vhi + Phi·Vlo ----
        #pragma unroll
        for (int u = 0; u < 2; u++) {           // 2 key-16 chunks
            uint32_t ph[2][4], pl[2][4];
            #pragma unroll
            for (int mt = 0; mt < 2; mt++)
                #pragma unroll
                for (int q = 0; q < 4; q++) {
                    const int nt = 2 * u + (q >> 1), rb = (q & 1) * 2;
                    float x = s[mt][nt][rb], y = s[mt][nt][rb + 1];
                    __nv_bfloat16 hx = __float2bfloat16(x), hy = __float2bfloat16(y);
                    ph[mt][q] = pack2(__bfloat162float(hx), __bfloat162float(hy));
                    pl[mt][q] = pack2(x - __bfloat162float(hx), y - __bfloat162float(hy));
                }
            #pragma unroll
            for (int vg = 0; vg < 4; vg++) {    // 4 n16 d-groups
                const uint32_t v = vg * 16 + krsel;
                const uint32_t voff = (v >> 1) * 128 + (v & 1) * 64 + u * 32 + ksel;
                uint32_t bv[4], bw[4];
                LDMX4(bv, Vs + SWZ(voff));             // V hi
                LDMX4(bw, Vs + 4096 + SWZ(voff));      // V lo
                #pragma unroll
                for (int mt = 0; mt < 2; mt++) {
                    MMA16816(o[mt][2 * vg],     ph[mt], bv[0], bv[1]);
                    MMA16816(o[mt][2 * vg + 1], ph[mt], bv[2], bv[3]);
                    MMA16816(o[mt][2 * vg],     pl[mt], bv[0], bv[1]);
                    MMA16816(o[mt][2 * vg + 1], pl[mt], bv[2], bv[3]);
                    MMA16816(o[mt][2 * vg],     ph[mt], bw[0], bw[1]);
                    MMA16816(o[mt][2 * vg + 1], ph[mt], bw[2], bw[3]);
                }
            }
        }

        // ---- deferred row-sum reductions ----
        #pragma unroll
        for (int mt = 0; mt < 2; mt++)
            #pragma unroll
            for (int h2 = 0; h2 < 2; h2++) {
                float sm = sum[mt][h2];
                sm += __shfl_xor_sync(0xffffffffu, sm, 1);
                sm += __shfl_xor_sync(0xffffffffu, sm, 2);
                lrow[mt][h2] += sm;
            }
    }

    // ---- finalize + write Zc [MR, hi(1024)|lo(1024)] ----
    const int b = bh >> 4, h = bh & 15;
    #pragma unroll
    for (int mt = 0; mt < 2; mt++) {
        const float inv0 = 1.f / lrow[mt][0], inv1 = 1.f / lrow[mt][1];
        #pragma unroll
        for (int nt = 0; nt < 8; nt++)
            #pragma unroll
            for (int r = 0; r < 4; r++) {
                int rl = w * 32 + mt * 16 + (lane >> 2) + (r >> 1) * 8;
                int d  = nt * 8 + (lane & 3) * 2 + (r & 1);
                float val = o[mt][nt][r] * ((r >> 1) ? inv1 : inv0);
                __nv_bfloat16 hi, lo; hilo(val, hi, lo);
                size_t idx = ((size_t)(b * 2048 + qb * 64 + rl)) * 2048 + h * 64 + d;
                Zc[idx] = hi;
                Zc[idx + 1024] = lo;
            }
    }
}

// ---------------------------------------------------------------------------
// Host launcher
// ---------------------------------------------------------------------------
extern "C" void kernel_launch(void* const* d_in, const int* in_sizes, int n_in,
                              void* d_out, int out_size)
{
    const float* query = (const float*)d_in[0];
    const float* key   = (const float*)d_in[1];
    const float* value = (const float*)d_in[2];
    const float* Wq = (const float*)d_in[3];  const float* bq = (const float*)d_in[4];
    const float* Wk = (const float*)d_in[5];  const float* bk = (const float*)d_in[6];
    const float* Wv = (const float*)d_in[7];  const float* bv = (const float*)d_in[8];
    const float* Wo = (const float*)d_in[9];  const float* bo = (const float*)d_in[10];

    __nv_bfloat16 *Qc, *Kc, *Vt, *Zc;
    cudaGetSymbolAddress((void**)&Qc, g_Qc);
    cudaGetSymbolAddress((void**)&Kc, g_Kc);
    cudaGetSymbolAddress((void**)&Vt, g_Vt);
    cudaGetSymbolAddress((void**)&Zc, g_Zc);

    cudaFuncSetAttribute(gemm_big<3>, cudaFuncAttributeMaxDynamicSharedMemorySize, GSMEM);
    cudaFuncSetAttribute(gemm_big<2>, cudaFuncAttributeMaxDynamicSharedMemorySize, GSMEM);
    cudaFuncSetAttribute(attn_mma, cudaFuncAttributeMaxDynamicSharedMemorySize, ATTN_SMEM);

    conv_w4<<<dim3(32, 32, 4), 256>>>(Wq, Wk, Wv, Wo);
    conv_x3<<<dim3(8192, 3), 256>>>(query, key, value);

    gemm_big<3><<<dim3(8, 128, 3), 128, GSMEM>>>(bq, bk, bv, nullptr);

    attn_mma<<<dim3(32, 64), 64, ATTN_SMEM>>>(Qc, Kc, Vt, Zc);

    gemm_big<2><<<dim3(8, 128, 1), 128, GSMEM>>>(bo, nullptr, nullptr, d_out);
}

// round 16
// speedup vs baseline: 1.4564x; 1.4564x over previous
#include <cuda_runtime.h>
#include <cuda_fp16.h>
#include <cstdint>

#define BATCH 4
#define SEQ   2048
#define DM    1024
#define NH    16
#define HD    64
#define MR    (BATCH*SEQ)   // 8192

// ---------------------------------------------------------------------------
// Scratch (__device__ globals: allocation-free rule). fp16 2-term scheme:
// A operands split hi+lo (exact to 2^-22), B operands plain fp16.
// ---------------------------------------------------------------------------
__device__ __align__(128) __half g_Xc[3][(size_t)MR * 2048];     // inputs [MR, hi(1024)|lo(1024)]
__device__ __align__(128) __half g_Wct[4][(size_t)1024 * 1024];  // W^T [n, k] plain fp16
__device__ __align__(128) __half g_Qc[(size_t)64 * SEQ * 128];   // [bh, s, hi64|lo64] (scaled log2e/8)
__device__ __align__(128) __half g_Kc[(size_t)64 * SEQ * 64];    // [bh, s, d] plain fp16
__device__ __align__(128) __half g_Vt[(size_t)64 * HD * SEQ];    // [bh, d, s] plain fp16
__device__ __align__(128) __half g_Zc[(size_t)MR * 2048];        // [MR, hi|lo]

// ---------------------------------------------------------------------------
// Helpers
// ---------------------------------------------------------------------------
__device__ __forceinline__ uint32_t smem_u32(const void* p) {
    uint32_t a;
    asm("{ .reg .u64 t; cvta.to.shared.u64 t, %1; cvt.u32.u64 %0, t; }" : "=r"(a) : "l"(p));
    return a;
}
#define SWZ(o) ((o) ^ (((o) >> 3) & 0x70))
#define CP16(dst, src) asm volatile("cp.async.cg.shared.global [%0], [%1], 16;" :: "r"(dst), "l"(src))
#define CP_COMMIT() asm volatile("cp.async.commit_group;" ::: "memory")
#define CP_WAIT0()  asm volatile("cp.async.wait_group 0;" ::: "memory")
#define CP_WAIT1()  asm volatile("cp.async.wait_group 1;" ::: "memory")

#define LDMX4(r, addr) asm volatile( \
    "ldmatrix.sync.aligned.m8n8.x4.shared.b16 {%0,%1,%2,%3}, [%4];" \
    : "=r"((r)[0]), "=r"((r)[1]), "=r"((r)[2]), "=r"((r)[3]) : "r"(addr))

#define MMA16816(c, a, b0, b1) asm volatile( \
    "mma.sync.aligned.m16n8k16.row.col.f32.f16.f16.f32 " \
    "{%0,%1,%2,%3},{%4,%5,%6,%7},{%8,%9},{%0,%1,%2,%3};" \
    : "+f"((c)[0]), "+f"((c)[1]), "+f"((c)[2]), "+f"((c)[3]) \
    : "r"((a)[0]), "r"((a)[1]), "r"((a)[2]), "r"((a)[3]), "r"(b0), "r"(b1))

#define EX2(d, x) asm("ex2.approx.f32 %0, %1;" : "=f"(d) : "f"(x))

__device__ __forceinline__ void hilo(float v, __half& h, __half& l) {
    h = __float2half_rn(v);
    l = __float2half_rn(v - __half2float(h));
}
__device__ __forceinline__ uint32_t pack2h(float x, float y) {
    __half2 t = __floats2half2_rn(x, y);
    return *(uint32_t*)&t;
}

// ---------------------------------------------------------------------------
// Converters
// ---------------------------------------------------------------------------
__global__ void conv_x3(const float* __restrict__ X0, const float* __restrict__ X1,
                        const float* __restrict__ X2) {
    const float* X = blockIdx.y == 0 ? X0 : (blockIdx.y == 1 ? X1 : X2);
    __half* Xc = g_Xc[blockIdx.y];
    int i = blockIdx.x * 256 + threadIdx.x;
    float4 v = ((const float4*)X)[i];
    int row = i >> 8;
    int c = (i & 255) * 4;
    __half h, l;
    size_t b = (size_t)row * 2048 + c;
    hilo(v.x, h, l); Xc[b + 0] = h; Xc[b + 1024 + 0] = l;
    hilo(v.y, h, l); Xc[b + 1] = h; Xc[b + 1024 + 1] = l;
    hilo(v.z, h, l); Xc[b + 2] = h; Xc[b + 1024 + 2] = l;
    hilo(v.w, h, l); Xc[b + 3] = h; Xc[b + 1024 + 3] = l;
}
__global__ void conv_w4(const float* __restrict__ W0, const float* __restrict__ W1,
                        const float* __restrict__ W2, const float* __restrict__ W3) {
    const float* W = blockIdx.z == 0 ? W0 : (blockIdx.z == 1 ? W1 :
                     (blockIdx.z == 2 ? W2 : W3));
    __half* Wct = g_Wct[blockIdx.z];
    __shared__ float t[32][33];
    int bx = blockIdx.x * 32, by = blockIdx.y * 32;  // bx: k, by: n
    int x = threadIdx.x & 31, y = threadIdx.x >> 5;
    #pragma unroll
    for (int i = 0; i < 32; i += 8) t[y + i][x] = W[(size_t)(bx + y + i) * 1024 + by + x];
    __syncthreads();
    #pragma unroll
    for (int i = 0; i < 32; i += 8) {
        // Wct[n][k] = W[k][n], plain fp16 (B operand)
        Wct[(size_t)(by + y + i) * 1024 + bx + x] = __float2half_rn(t[x][y + i]);
    }
}

// ---------------------------------------------------------------------------
// mma.sync GEMM (fp16 2-term): CTA 64x128, 4 warps (32x64 each), BK=64,
// NC=32 (K'=2048: A=[hi|lo], B plain repeats), 3-stage pipeline, 3 CTAs/SM.
// MODE 3: merged QKV (z sel; Q scaled log2e/8, hi/lo out; K plain; V^T plain)
// MODE 2: fp32 out.
// ---------------------------------------------------------------------------
#define GSMEM (3 * 24576 + 1024)

template <int MODE>
__global__ void __launch_bounds__(128, 3)
gemm_big(const float* __restrict__ bias0, const float* __restrict__ bias1,
         const float* __restrict__ bias2, void* __restrict__ Cout)
{
    extern __shared__ char dsm[];
    const uint32_t sb = (smem_u32(dsm) + 1023u) & ~1023u;
    const int tid = threadIdx.x, w = tid >> 5, lane = tid & 31;
    const int wm = w >> 1, wn = w & 1;               // 2 x 2 warp grid
    const int m0 = blockIdx.y * 64, n0 = blockIdx.x * 128;
    const int z = (MODE == 3) ? blockIdx.z : 3;

    const __half* A = (MODE == 3) ? g_Xc[z] : g_Zc;
    const __half* Bw = g_Wct[z];
    const float* bias = (MODE == 3) ? (z == 0 ? bias0 : (z == 1 ? bias1 : bias2))
                                    : bias0;

    auto load_chunk = [&](int c, int buf) {
        int ka = c * 64;                            // A: [hi|lo] linear 0..2047
        int kb = (c < 16) ? c * 64 : (c - 16) * 64; // B: plain, repeats for lo pass
        uint32_t ab = sb + buf * 24576, bb = ab + 8192;
        #pragma unroll
        for (int i = 0; i < 4; i++) {               // A: 64 rows x 8 slots
            int u = tid + i * 128, row = u >> 3, sl = u & 7;
            CP16(ab + SWZ(row * 128 + sl * 16), A + (size_t)(m0 + row) * 2048 + ka + sl * 8);
        }
        #pragma unroll
        for (int i = 0; i < 8; i++) {               // B: 128 rows x 8 slots
            int u = tid + i * 128, row = u >> 3, sl = u & 7;
            CP16(bb + SWZ(row * 128 + sl * 16), Bw + (size_t)(n0 + row) * 1024 + kb + sl * 8);
        }
    };

    float acc[2][8][4];
    #pragma unroll
    for (int mt = 0; mt < 2; mt++)
        #pragma unroll
        for (int nt = 0; nt < 8; nt++)
            #pragma unroll
            for (int r = 0; r < 4; r++) acc[mt][nt][r] = 0.f;

    const int NC = 32;
    load_chunk(0, 0); CP_COMMIT();
    load_chunk(1, 1); CP_COMMIT();
    for (int c = 0; c < NC; c++) {
        if (c + 1 < NC) CP_WAIT1(); else CP_WAIT0();
        __syncthreads();     // also: compute(c-1) done -> buffer (c+2)%3 free
        if (c + 2 < NC) { load_chunk(c + 2, (c + 2) % 3); CP_COMMIT(); }

        const uint32_t ab = sb + (c % 3) * 24576, bb = ab + 8192;
        uint32_t a[2][2][4], b[2][4];
        auto lda = [&](uint32_t (&d)[2][4], int kkv) {
            #pragma unroll
            for (int mt = 0; mt < 2; mt++)
                LDMX4(d[mt], ab + SWZ((wm * 32 + mt * 16 + (lane & 15)) * 128
                                      + kkv * 32 + (lane >> 4) * 16));
        };
        auto ldb = [&](uint32_t (&d)[4], int kkv, int pv) {
            LDMX4(d, bb + SWZ((wn * 64 + pv * 16 + ((lane >> 4) << 3) + (lane & 7)) * 128
                              + kkv * 32 + ((lane >> 3) & 1) * 16));
        };
        lda(a[0], 0); ldb(b[0], 0, 0);
        #pragma unroll
        for (int kk = 0; kk < 4; kk++) {
            #pragma unroll
            for (int p = 0; p < 4; p++) {
                const int cur = (kk * 4 + p) & 1;
                if (p < 3)       ldb(b[cur ^ 1], kk, p + 1);
                else if (kk < 3) { lda(a[(kk + 1) & 1], kk + 1); ldb(b[cur ^ 1], kk + 1, 0); }
                #pragma unroll
                for (int mt = 0; mt < 2; mt++) {
                    MMA16816(acc[mt][2 * p],     a[kk & 1][mt], b[cur][0], b[cur][1]);
                    MMA16816(acc[mt][2 * p + 1], a[kk & 1][mt], b[cur][2], b[cur][3]);
                }
            }
        }
    }

    // epilogue
    #pragma unroll
    for (int mt = 0; mt < 2; mt++)
        #pragma unroll
        for (int nt = 0; nt < 8; nt++)
            #pragma unroll
            for (int r = 0; r < 4; r++) {
                int row = m0 + wm * 32 + mt * 16 + (lane >> 2) + (r >> 1) * 8;
                int col = n0 + wn * 64 + nt * 8 + (lane & 3) * 2 + (r & 1);
                float val = acc[mt][nt][r] + bias[col];
                if (MODE == 2) {
                    ((float*)Cout)[(size_t)row * 1024 + col] = val;
                } else {
                    int bh = (row >> 11) * 16 + (col >> 6), s = row & 2047, d = col & 63;
                    if (z == 0) {
                        val *= 0.1803368801111f;   // (1/8)*log2(e): log2-domain scores
                        __half h, l; hilo(val, h, l);
                        size_t o = ((size_t)bh * 2048 + s) * 128 + d;
                        g_Qc[o] = h; g_Qc[o + 64] = l;
                    } else if (z == 1) {
                        g_Kc[((size_t)bh * 2048 + s) * 64 + d] = __float2half_rn(val);
                    } else {
                        g_Vt[((size_t)bh * 64 + d) * 2048 + s] = __float2half_rn(val);
                    }
                }
            }
}

// ---------------------------------------------------------------------------
// Flash attention (fp16 2-term): CTA = (qb, bh) = 128 q-rows, 4 warps of 32
// q-rows, 32-key double-buffered blocks, 2 CTAs/SM, resident aQ (hi+lo),
// K and V plain fp16 (B operands), MUFU ex2 softmax, no online max.
// smem: Q 32K | buf0 (K 4K + V 4K) | buf1 (8K) = 48.5KB
// ---------------------------------------------------------------------------
#define ATTN_SMEM (1024 + 32768 + 2 * 8192)

__global__ void __launch_bounds__(128, 2)
attn_mma(const __half* __restrict__ Qc, const __half* __restrict__ Kc,
         const __half* __restrict__ Vt, __half* __restrict__ Zc)
{
    extern __shared__ char dsm[];
    const uint32_t sb = (smem_u32(dsm) + 1023u) & ~1023u;
    const uint32_t Qs = sb;                        // 32KB
    const int tid = threadIdx.x, w = tid >> 5, lane = tid & 31;
    const int qb = blockIdx.x, bh = blockIdx.y;

    auto load_kv = [&](int kb, uint32_t buf) {
        const uint32_t Ks = buf, Vs = buf + 4096;
        const size_t kbase = ((size_t)bh * 2048 + kb * 32) * 64;
        #pragma unroll
        for (int i = 0; i < 2; i++) {           // K: 32 keys x 128B
            int u = tid + i * 128, key = u >> 3, sl = u & 7;
            CP16(Ks + SWZ(key * 128 + sl * 16),
                 Kc + kbase + (size_t)key * 64 + sl * 8);
        }
        #pragma unroll
        for (int i = 0; i < 2; i++) {           // V: 64 d x 64B (2 d per row)
            int u = tid + i * 128, d = u >> 2, sl = u & 3;
            CP16(Vs + SWZ((d >> 1) * 128 + (d & 1) * 64 + sl * 16),
                 Vt + ((size_t)bh * 64 + d) * 2048 + kb * 32 + sl * 8);
        }
    };

    // ---- preamble: Q (128 rows x 256B = hi|lo) + first K/V block ----
    {
        const size_t qbase = ((size_t)bh * 2048 + qb * 128) * 128;
        #pragma unroll
        for (int i = 0; i < 16; i++) {
            int u = tid + i * 128, row = u >> 4, seg = u & 15;
            CP16(Qs + SWZ((row * 2 + (seg >> 3)) * 128 + (seg & 7) * 16),
                 Qc + qbase + (size_t)row * 128 + seg * 8);
        }
        CP_COMMIT();
    }
    load_kv(0, sb + 32768); CP_COMMIT();
    CP_WAIT1();
    __syncthreads();

    // ---- Q A-fragments: 2 m16 x (4 k16 hi + 4 k16 lo), resident (64 regs) ----
    uint32_t aQ[2][8][4];
    #pragma unroll
    for (int mt = 0; mt < 2; mt++)
        #pragma unroll
        for (int t = 0; t < 8; t++)
            LDMX4(aQ[mt][t],
                  Qs + SWZ(((w * 32 + mt * 16 + (lane & 15)) * 2 + (t >> 2)) * 128
                           + (t & 3) * 32 + (lane >> 4) * 16));

    float lrow[2][2] = {{0.f, 0.f}, {0.f, 0.f}};
    float o[2][8][4];
    #pragma unroll
    for (int mt = 0; mt < 2; mt++)
        #pragma unroll
        for (int nt = 0; nt < 8; nt++)
            #pragma unroll
            for (int r = 0; r < 4; r++) o[mt][nt][r] = 0.f;

    const uint32_t ksel = ((lane >> 3) & 1) * 16;
    const uint32_t krsel = ((lane >> 4) << 3) + (lane & 7);

    for (int kb = 0; kb < 64; kb++) {
        __syncthreads();
        if (kb + 1 < 64) { load_kv(kb + 1, sb + 32768 + ((kb + 1) & 1) * 8192);
                           CP_COMMIT(); CP_WAIT1(); }
        else CP_WAIT0();
        __syncthreads();
        const uint32_t Ks = sb + 32768 + (kb & 1) * 8192, Vs = Ks + 4096;

        // ---- scores: 32 rows x 32 keys, 2 segments (Qhi·K + Qlo·K) ----
        float s[2][4][4];
        #pragma unroll
        for (int mt = 0; mt < 2; mt++)
            #pragma unroll
            for (int nt = 0; nt < 4; nt++)
                #pragma unroll
                for (int r = 0; r < 4; r++) s[mt][nt][r] = 0.f;

        #pragma unroll
        for (int kb4 = 0; kb4 < 4; kb4++) {
            const uint32_t kbyte = kb4 * 32 + ksel;
            uint32_t b0[4], b1[4];
            LDMX4(b0, Ks + SWZ(krsel * 128 + kbyte));             // K, keys 0-15
            LDMX4(b1, Ks + SWZ((16 + krsel) * 128 + kbyte));      // K, keys 16-31
            #pragma unroll
            for (int mt = 0; mt < 2; mt++) {
                const uint32_t* qh = aQ[mt][kb4];
                const uint32_t* ql = aQ[mt][kb4 + 4];
                MMA16816(s[mt][0], qh, b0[0], b0[1]);   // Qhi·K
                MMA16816(s[mt][1], qh, b0[2], b0[3]);
                MMA16816(s[mt][2], qh, b1[0], b1[1]);
                MMA16816(s[mt][3], qh, b1[2], b1[3]);
                MMA16816(s[mt][0], ql, b0[0], b0[1]);   // Qlo·K
                MMA16816(s[mt][1], ql, b0[2], b0[3]);
                MMA16816(s[mt][2], ql, b1[0], b1[1]);
                MMA16816(s[mt][3], ql, b1[2], b1[3]);
            }
        }

        // ---- P = 2^s (MUFU ex2; log2-domain scores) + row sums ----
        float sum[2][2] = {{0.f, 0.f}, {0.f, 0.f}};
        #pragma unroll
        for (int mt = 0; mt < 2; mt++)
            #pragma unroll
            for (int nt = 0; nt < 4; nt++) {
                EX2(s[mt][nt][0], s[mt][nt][0]);
                EX2(s[mt][nt][1], s[mt][nt][1]);
                sum[mt][0] += s[mt][nt][0] + s[mt][nt][1];
                EX2(s[mt][nt][2], s[mt][nt][2]);
                EX2(s[mt][nt][3], s[mt][nt][3]);
                sum[mt][1] += s[mt][nt][2] + s[mt][nt][3];
            }

        // ---- PV: O[32,64] += (Phi + Plo)·V, V plain fp16 ----
        #pragma unroll
        for (int u = 0; u < 2; u++) {           // 2 key-16 chunks
            uint32_t ph[2][4], pl[2][4];
            #pragma unroll
            for (int mt = 0; mt < 2; mt++)
                #pragma unroll
                for (int q = 0; q < 4; q++) {
                    const int nt = 2 * u + (q >> 1), rb = (q & 1) * 2;
                    float x = s[mt][nt][rb], y = s[mt][nt][rb + 1];
                    __half hx = __float2half_rn(x), hy = __float2half_rn(y);
                    ph[mt][q] = pack2h(__half2float(hx), __half2float(hy));
                    pl[mt][q] = pack2h(x - __half2float(hx), y - __half2float(hy));
                }
            #pragma unroll
            for (int vg = 0; vg < 4; vg++) {    // 4 n16 d-groups
                const uint32_t v = vg * 16 + krsel;
                const uint32_t voff = (v >> 1) * 128 + (v & 1) * 64 + u * 32 + ksel;
                uint32_t bv[4];
                LDMX4(bv, Vs + SWZ(voff));
                #pragma unroll
                for (int mt = 0; mt < 2; mt++) {
                    MMA16816(o[mt][2 * vg],     ph[mt], bv[0], bv[1]);
                    MMA16816(o[mt][2 * vg + 1], ph[mt], bv[2], bv[3]);
                    MMA16816(o[mt][2 * vg],     pl[mt], bv[0], bv[1]);
                    MMA16816(o[mt][2 * vg + 1], pl[mt], bv[2], bv[3]);
                }
            }
        }

        // ---- deferred row-sum reductions ----
        #pragma unroll
        for (int mt = 0; mt < 2; mt++)
            #pragma unroll
            for (int h2 = 0; h2 < 2; h2++) {
                float sm = sum[mt][h2];
                sm += __shfl_xor_sync(0xffffffffu, sm, 1);
                sm += __shfl_xor_sync(0xffffffffu, sm, 2);
                lrow[mt][h2] += sm;
            }
    }

    // ---- finalize + write Zc [MR, hi(1024)|lo(1024)] ----
    const int b = bh >> 4, h = bh & 15;
    #pragma unroll
    for (int mt = 0; mt < 2; mt++) {
        const float inv0 = 1.f / lrow[mt][0], inv1 = 1.f / lrow[mt][1];
        #pragma unroll
        for (int nt = 0; nt < 8; nt++)
            #pragma unroll
            for (int r = 0; r < 4; r++) {
                int rl = w * 32 + mt * 16 + (lane >> 2) + (r >> 1) * 8;
                int d  = nt * 8 + (lane & 3) * 2 + (r & 1);
                float val = o[mt][nt][r] * ((r >> 1) ? inv1 : inv0);
                __half hi, lo; hilo(val, hi, lo);
                size_t idx = ((size_t)(b * 2048 + qb * 128 + rl)) * 2048 + h * 64 + d;
                Zc[idx] = hi;
                Zc[idx + 1024] = lo;
            }
    }
}

// ---------------------------------------------------------------------------
// Host launcher
// ---------------------------------------------------------------------------
extern "C" void kernel_launch(void* const* d_in, const int* in_sizes, int n_in,
                              void* d_out, int out_size)
{
    const float* query = (const float*)d_in[0];
    const float* key   = (const float*)d_in[1];
    const float* value = (const float*)d_in[2];
    const float* Wq = (const float*)d_in[3];  const float* bq = (const float*)d_in[4];
    const float* Wk = (const float*)d_in[5];  const float* bk = (const float*)d_in[6];
    const float* Wv = (const float*)d_in[7];  const float* bv = (const float*)d_in[8];
    const float* Wo = (const float*)d_in[9];  const float* bo = (const float*)d_in[10];

    __half *Qc, *Kc, *Vt, *Zc;
    cudaGetSymbolAddress((void**)&Qc, g_Qc);
    cudaGetSymbolAddress((void**)&Kc, g_Kc);
    cudaGetSymbolAddress((void**)&Vt, g_Vt);
    cudaGetSymbolAddress((void**)&Zc, g_Zc);

    cudaFuncSetAttribute(gemm_big<3>, cudaFuncAttributeMaxDynamicSharedMemorySize, GSMEM);
    cudaFuncSetAttribute(gemm_big<2>, cudaFuncAttributeMaxDynamicSharedMemorySize, GSMEM);
    cudaFuncSetAttribute(attn_mma, cudaFuncAttributeMaxDynamicSharedMemorySize, ATTN_SMEM);

    conv_w4<<<dim3(32, 32, 4), 256>>>(Wq, Wk, Wv, Wo);
    conv_x3<<<dim3(8192, 3), 256>>>(query, key, value);

    gemm_big<3><<<dim3(8, 128, 3), 128, GSMEM>>>(bq, bk, bv, nullptr);

    attn_mma<<<dim3(16, 64), 128, ATTN_SMEM>>>(Qc, Kc, Vt, Zc);

    gemm_big<2><<<dim3(8, 128, 1), 128, GSMEM>>>(bo, nullptr, nullptr, d_out);
}

// round 17
// speedup vs baseline: 1.6389x; 1.1253x over previous
#include <cuda_runtime.h>
#include <cuda_fp16.h>
#include <cstdint>

#define BATCH 4
#define SEQ   2048
#define DM    1024
#define NH    16
#define HD    64
#define MR    (BATCH*SEQ)   // 8192

// ---------------------------------------------------------------------------
// Scratch (__device__ globals). fp16 scheme: X/Z (GEMM A-operands) split
// hi+lo; W/K/V plain fp16; Q plain fp16 (scores only need absolute accuracy
// in the log2 domain); P split hi+lo in registers.
// ---------------------------------------------------------------------------
__device__ __align__(128) __half g_Xc[3][(size_t)MR * 2048];     // inputs [MR, hi(1024)|lo(1024)]
__device__ __align__(128) __half g_Wct[4][(size_t)1024 * 1024];  // W^T [n, k] plain fp16
__device__ __align__(128) __half g_Qc[(size_t)64 * SEQ * 64];    // [bh, s, d] plain (scaled log2e/8)
__device__ __align__(128) __half g_Kc[(size_t)64 * SEQ * 64];    // [bh, s, d] plain fp16
__device__ __align__(128) __half g_Vt[(size_t)64 * HD * SEQ];    // [bh, d, s] plain fp16
__device__ __align__(128) __half g_Zc[(size_t)MR * 2048];        // [MR, hi|lo]

// ---------------------------------------------------------------------------
// Helpers
// ---------------------------------------------------------------------------
__device__ __forceinline__ uint32_t smem_u32(const void* p) {
    uint32_t a;
    asm("{ .reg .u64 t; cvta.to.shared.u64 t, %1; cvt.u32.u64 %0, t; }" : "=r"(a) : "l"(p));
    return a;
}
#define SWZ(o) ((o) ^ (((o) >> 3) & 0x70))
#define CP16(dst, src) asm volatile("cp.async.cg.shared.global [%0], [%1], 16;" :: "r"(dst), "l"(src))
#define CP_COMMIT() asm volatile("cp.async.commit_group;" ::: "memory")
#define CP_WAIT0()  asm volatile("cp.async.wait_group 0;" ::: "memory")
#define CP_WAIT1()  asm volatile("cp.async.wait_group 1;" ::: "memory")

#define LDMX4(r, addr) asm volatile( \
    "ldmatrix.sync.aligned.m8n8.x4.shared.b16 {%0,%1,%2,%3}, [%4];" \
    : "=r"((r)[0]), "=r"((r)[1]), "=r"((r)[2]), "=r"((r)[3]) : "r"(addr))

#define MMA16816(c, a, b0, b1) asm volatile( \
    "mma.sync.aligned.m16n8k16.row.col.f32.f16.f16.f32 " \
    "{%0,%1,%2,%3},{%4,%5,%6,%7},{%8,%9},{%0,%1,%2,%3};" \
    : "+f"((c)[0]), "+f"((c)[1]), "+f"((c)[2]), "+f"((c)[3]) \
    : "r"((a)[0]), "r"((a)[1]), "r"((a)[2]), "r"((a)[3]), "r"(b0), "r"(b1))

#define EX2(d, x) asm("ex2.approx.f32 %0, %1;" : "=f"(d) : "f"(x))

__device__ __forceinline__ void hilo(float v, __half& h, __half& l) {
    h = __float2half_rn(v);
    l = __float2half_rn(v - __half2float(h));
}
__device__ __forceinline__ uint32_t pack2h(float x, float y) {
    __half2 t = __floats2half2_rn(x, y);
    return *(uint32_t*)&t;
}

// ---------------------------------------------------------------------------
// Converters
// ---------------------------------------------------------------------------
__global__ void conv_x3(const float* __restrict__ X0, const float* __restrict__ X1,
                        const float* __restrict__ X2) {
    const float* X = blockIdx.y == 0 ? X0 : (blockIdx.y == 1 ? X1 : X2);
    __half* Xc = g_Xc[blockIdx.y];
    int i = blockIdx.x * 256 + threadIdx.x;
    float4 v = ((const float4*)X)[i];
    int row = i >> 8;
    int c = (i & 255) * 4;
    __half h, l;
    size_t b = (size_t)row * 2048 + c;
    hilo(v.x, h, l); Xc[b + 0] = h; Xc[b + 1024 + 0] = l;
    hilo(v.y, h, l); Xc[b + 1] = h; Xc[b + 1024 + 1] = l;
    hilo(v.z, h, l); Xc[b + 2] = h; Xc[b + 1024 + 2] = l;
    hilo(v.w, h, l); Xc[b + 3] = h; Xc[b + 1024 + 3] = l;
}
__global__ void conv_w4(const float* __restrict__ W0, const float* __restrict__ W1,
                        const float* __restrict__ W2, const float* __restrict__ W3) {
    const float* W = blockIdx.z == 0 ? W0 : (blockIdx.z == 1 ? W1 :
                     (blockIdx.z == 2 ? W2 : W3));
    __half* Wct = g_Wct[blockIdx.z];
    __shared__ float t[32][33];
    int bx = blockIdx.x * 32, by = blockIdx.y * 32;  // bx: k, by: n
    int x = threadIdx.x & 31, y = threadIdx.x >> 5;
    #pragma unroll
    for (int i = 0; i < 32; i += 8) t[y + i][x] = W[(size_t)(bx + y + i) * 1024 + by + x];
    __syncthreads();
    #pragma unroll
    for (int i = 0; i < 32; i += 8) {
        Wct[(size_t)(by + y + i) * 1024 + bx + x] = __float2half_rn(t[x][y + i]);
    }
}

// ---------------------------------------------------------------------------
// mma.sync GEMM (fp16 2-term): CTA 64x128, 4 warps (32x64 each), BK=64,
// NC=32 (K'=2048: A=[hi|lo], B plain repeats), 3-stage pipeline, 3 CTAs/SM.
// MODE 3: merged QKV (z sel; Q plain scaled log2e/8; K plain; V^T plain)
// MODE 2: fp32 out.
// ---------------------------------------------------------------------------
#define GSMEM (3 * 24576 + 1024)

template <int MODE>
__global__ void __launch_bounds__(128, 3)
gemm_big(const float* __restrict__ bias0, const float* __restrict__ bias1,
         const float* __restrict__ bias2, void* __restrict__ Cout)
{
    extern __shared__ char dsm[];
    const uint32_t sb = (smem_u32(dsm) + 1023u) & ~1023u;
    const int tid = threadIdx.x, w = tid >> 5, lane = tid & 31;
    const int wm = w >> 1, wn = w & 1;               // 2 x 2 warp grid
    const int m0 = blockIdx.y * 64, n0 = blockIdx.x * 128;
    const int z = (MODE == 3) ? blockIdx.z : 3;

    const __half* A = (MODE == 3) ? g_Xc[z] : g_Zc;
    const __half* Bw = g_Wct[z];
    const float* bias = (MODE == 3) ? (z == 0 ? bias0 : (z == 1 ? bias1 : bias2))
                                    : bias0;

    auto load_chunk = [&](int c, int buf) {
        int ka = c * 64;                            // A: [hi|lo] linear 0..2047
        int kb = (c < 16) ? c * 64 : (c - 16) * 64; // B: plain, repeats for lo pass
        uint32_t ab = sb + buf * 24576, bb = ab + 8192;
        #pragma unroll
        for (int i = 0; i < 4; i++) {               // A: 64 rows x 8 slots
            int u = tid + i * 128, row = u >> 3, sl = u & 7;
            CP16(ab + SWZ(row * 128 + sl * 16), A + (size_t)(m0 + row) * 2048 + ka + sl * 8);
        }
        #pragma unroll
        for (int i = 0; i < 8; i++) {               // B: 128 rows x 8 slots
            int u = tid + i * 128, row = u >> 3, sl = u & 7;
            CP16(bb + SWZ(row * 128 + sl * 16), Bw + (size_t)(n0 + row) * 1024 + kb + sl * 8);
        }
    };

    float acc[2][8][4];
    #pragma unroll
    for (int mt = 0; mt < 2; mt++)
        #pragma unroll
        for (int nt = 0; nt < 8; nt++)
            #pragma unroll
            for (int r = 0; r < 4; r++) acc[mt][nt][r] = 0.f;

    const int NC = 32;
    load_chunk(0, 0); CP_COMMIT();
    load_chunk(1, 1); CP_COMMIT();
    for (int c = 0; c < NC; c++) {
        if (c + 1 < NC) CP_WAIT1(); else CP_WAIT0();
        __syncthreads();     // also: compute(c-1) done -> buffer (c+2)%3 free
        if (c + 2 < NC) { load_chunk(c + 2, (c + 2) % 3); CP_COMMIT(); }

        const uint32_t ab = sb + (c % 3) * 24576, bb = ab + 8192;
        uint32_t a[2][2][4], b[2][4];
        auto lda = [&](uint32_t (&d)[2][4], int kkv) {
            #pragma unroll
            for (int mt = 0; mt < 2; mt++)
                LDMX4(d[mt], ab + SWZ((wm * 32 + mt * 16 + (lane & 15)) * 128
                                      + kkv * 32 + (lane >> 4) * 16));
        };
        auto ldb = [&](uint32_t (&d)[4], int kkv, int pv) {
            LDMX4(d, bb + SWZ((wn * 64 + pv * 16 + ((lane >> 4) << 3) + (lane & 7)) * 128
                              + kkv * 32 + ((lane >> 3) & 1) * 16));
        };
        lda(a[0], 0); ldb(b[0], 0, 0);
        #pragma unroll
        for (int kk = 0; kk < 4; kk++) {
            #pragma unroll
            for (int p = 0; p < 4; p++) {
                const int cur = (kk * 4 + p) & 1;
                if (p < 3)       ldb(b[cur ^ 1], kk, p + 1);
                else if (kk < 3) { lda(a[(kk + 1) & 1], kk + 1); ldb(b[cur ^ 1], kk + 1, 0); }
                #pragma unroll
                for (int mt = 0; mt < 2; mt++) {
                    MMA16816(acc[mt][2 * p],     a[kk & 1][mt], b[cur][0], b[cur][1]);
                    MMA16816(acc[mt][2 * p + 1], a[kk & 1][mt], b[cur][2], b[cur][3]);
                }
            }
        }
    }

    // epilogue
    #pragma unroll
    for (int mt = 0; mt < 2; mt++)
        #pragma unroll
        for (int nt = 0; nt < 8; nt++)
            #pragma unroll
            for (int r = 0; r < 4; r++) {
                int row = m0 + wm * 32 + mt * 16 + (lane >> 2) + (r >> 1) * 8;
                int col = n0 + wn * 64 + nt * 8 + (lane & 3) * 2 + (r & 1);
                float val = acc[mt][nt][r] + bias[col];
                if (MODE == 2) {
                    ((float*)Cout)[(size_t)row * 1024 + col] = val;
                } else {
                    int bh = (row >> 11) * 16 + (col >> 6), s = row & 2047, d = col & 63;
                    if (z == 0) {
                        // plain Q, log2-domain scale folded in
                        g_Qc[((size_t)bh * 2048 + s) * 64 + d] =
                            __float2half_rn(val * 0.1803368801111f);
                    } else if (z == 1) {
                        g_Kc[((size_t)bh * 2048 + s) * 64 + d] = __float2half_rn(val);
                    } else {
                        g_Vt[((size_t)bh * 64 + d) * 2048 + s] = __float2half_rn(val);
                    }
                }
            }
}

// ---------------------------------------------------------------------------
// Flash attention (fp16, plain Q·K scores + compensated PV):
// CTA = (qb, bh) = 128 q-rows, 4 warps of 32 q-rows, 32-key double-buffered
// blocks, 2 CTAs/SM, resident plain-Q fragments, MUFU ex2, no online max.
// Scores: 32 MMAs/warp/block (plain QK); PV: 64 (Phi+Plo vs V).
// smem: Q 16K | buf0 (K 4K + V 4K) | buf1 (8K) = 32.5KB
// ---------------------------------------------------------------------------
#define ATTN_SMEM (1024 + 16384 + 2 * 8192)

__global__ void __launch_bounds__(128, 2)
attn_mma(const __half* __restrict__ Qc, const __half* __restrict__ Kc,
         const __half* __restrict__ Vt, __half* __restrict__ Zc)
{
    extern __shared__ char dsm[];
    const uint32_t sb = (smem_u32(dsm) + 1023u) & ~1023u;
    const uint32_t Qs = sb;                        // 16KB
    const int tid = threadIdx.x, w = tid >> 5, lane = tid & 31;
    const int qb = blockIdx.x, bh = blockIdx.y;

    auto load_kv = [&](int kb, uint32_t buf) {
        const uint32_t Ks = buf, Vs = buf + 4096;
        const size_t kbase = ((size_t)bh * 2048 + kb * 32) * 64;
        #pragma unroll
        for (int i = 0; i < 2; i++) {           // K: 32 keys x 128B
            int u = tid + i * 128, key = u >> 3, sl = u & 7;
            CP16(Ks + SWZ(key * 128 + sl * 16),
                 Kc + kbase + (size_t)key * 64 + sl * 8);
        }
        #pragma unroll
        for (int i = 0; i < 2; i++) {           // V: 64 d x 64B (2 d per row)
            int u = tid + i * 128, d = u >> 2, sl = u & 3;
            CP16(Vs + SWZ((d >> 1) * 128 + (d & 1) * 64 + sl * 16),
                 Vt + ((size_t)bh * 64 + d) * 2048 + kb * 32 + sl * 8);
        }
    };

    // ---- preamble: Q (128 rows x 128B) + first K/V block ----
    {
        const size_t qbase = ((size_t)bh * 2048 + qb * 128) * 64;
        #pragma unroll
        for (int i = 0; i < 8; i++) {
            int u = tid + i * 128, row = u >> 3, sl = u & 7;
            CP16(Qs + SWZ(row * 128 + sl * 16),
                 Qc + qbase + (size_t)row * 64 + sl * 8);
        }
        CP_COMMIT();
    }
    load_kv(0, sb + 16384); CP_COMMIT();
    CP_WAIT1();
    __syncthreads();

    // ---- Q A-fragments: 2 m16 x 4 k16, resident (32 regs) ----
    uint32_t aQ[2][4][4];
    #pragma unroll
    for (int mt = 0; mt < 2; mt++)
        #pragma unroll
        for (int t = 0; t < 4; t++)
            LDMX4(aQ[mt][t],
                  Qs + SWZ((w * 32 + mt * 16 + (lane & 15)) * 128
                           + t * 32 + (lane >> 4) * 16));

    float lrow[2][2] = {{0.f, 0.f}, {0.f, 0.f}};
    float o[2][8][4];
    #pragma unroll
    for (int mt = 0; mt < 2; mt++)
        #pragma unroll
        for (int nt = 0; nt < 8; nt++)
            #pragma unroll
            for (int r = 0; r < 4; r++) o[mt][nt][r] = 0.f;

    const uint32_t ksel = ((lane >> 3) & 1) * 16;
    const uint32_t krsel = ((lane >> 4) << 3) + (lane & 7);

    for (int kb = 0; kb < 64; kb++) {
        __syncthreads();
        if (kb + 1 < 64) { load_kv(kb + 1, sb + 16384 + ((kb + 1) & 1) * 8192);
                           CP_COMMIT(); CP_WAIT1(); }
        else CP_WAIT0();
        __syncthreads();
        const uint32_t Ks = sb + 16384 + (kb & 1) * 8192, Vs = Ks + 4096;

        // ---- scores: 32 rows x 32 keys, plain Q·K ----
        float s[2][4][4];
        #pragma unroll
        for (int mt = 0; mt < 2; mt++)
            #pragma unroll
            for (int nt = 0; nt < 4; nt++)
                #pragma unroll
                for (int r = 0; r < 4; r++) s[mt][nt][r] = 0.f;

        #pragma unroll
        for (int kb4 = 0; kb4 < 4; kb4++) {
            const uint32_t kbyte = kb4 * 32 + ksel;
            uint32_t b0[4], b1[4];
            LDMX4(b0, Ks + SWZ(krsel * 128 + kbyte));             // K, keys 0-15
            LDMX4(b1, Ks + SWZ((16 + krsel) * 128 + kbyte));      // K, keys 16-31
            #pragma unroll
            for (int mt = 0; mt < 2; mt++) {
                const uint32_t* q = aQ[mt][kb4];
                MMA16816(s[mt][0], q, b0[0], b0[1]);
                MMA16816(s[mt][1], q, b0[2], b0[3]);
                MMA16816(s[mt][2], q, b1[0], b1[1]);
                MMA16816(s[mt][3], q, b1[2], b1[3]);
            }
        }

        // ---- P = 2^s (MUFU ex2; log2-domain scores) + row sums ----
        float sum[2][2] = {{0.f, 0.f}, {0.f, 0.f}};
        #pragma unroll
        for (int mt = 0; mt < 2; mt++)
            #pragma unroll
            for (int nt = 0; nt < 4; nt++) {
                EX2(s[mt][nt][0], s[mt][nt][0]);
                EX2(s[mt][nt][1], s[mt][nt][1]);
                sum[mt][0] += s[mt][nt][0] + s[mt][nt][1];
                EX2(s[mt][nt][2], s[mt][nt][2]);
                EX2(s[mt][nt][3], s[mt][nt][3]);
                sum[mt][1] += s[mt][nt][2] + s[mt][nt][3];
            }

        // ---- PV: O[32,64] += (Phi + Plo)·V, V plain fp16 ----
        #pragma unroll
        for (int u = 0; u < 2; u++) {           // 2 key-16 chunks
            uint32_t ph[2][4], pl[2][4];
            #pragma unroll
            for (int mt = 0; mt < 2; mt++)
                #pragma unroll
                for (int q = 0; q < 4; q++) {
                    const int nt = 2 * u + (q >> 1), rb = (q & 1) * 2;
                    float x = s[mt][nt][rb], y = s[mt][nt][rb + 1];
                    __half hx = __float2half_rn(x), hy = __float2half_rn(y);
                    ph[mt][q] = pack2h(__half2float(hx), __half2float(hy));
                    pl[mt][q] = pack2h(x - __half2float(hx), y - __half2float(hy));
                }
            #pragma unroll
            for (int vg = 0; vg < 4; vg++) {    // 4 n16 d-groups
                const uint32_t v = vg * 16 + krsel;
                const uint32_t voff = (v >> 1) * 128 + (v & 1) * 64 + u * 32 + ksel;
                uint32_t bv[4];
                LDMX4(bv, Vs + SWZ(voff));
                #pragma unroll
                for (int mt = 0; mt < 2; mt++) {
                    MMA16816(o[mt][2 * vg],     ph[mt], bv[0], bv[1]);
                    MMA16816(o[mt][2 * vg + 1], ph[mt], bv[2], bv[3]);
                    MMA16816(o[mt][2 * vg],     pl[mt], bv[0], bv[1]);
                    MMA16816(o[mt][2 * vg + 1], pl[mt], bv[2], bv[3]);
                }
            }
        }

        // ---- deferred row-sum reductions ----
        #pragma unroll
        for (int mt = 0; mt < 2; mt++)
            #pragma unroll
            for (int h2 = 0; h2 < 2; h2++) {
                float sm = sum[mt][h2];
                sm += __shfl_xor_sync(0xffffffffu, sm, 1);
                sm += __shfl_xor_sync(0xffffffffu, sm, 2);
                lrow[mt][h2] += sm;
            }
    }

    // ---- finalize + write Zc [MR, hi(1024)|lo(1024)] ----
    const int b = bh >> 4, h = bh & 15;
    #pragma unroll
    for (int mt = 0; mt < 2; mt++) {
        const float inv0 = 1.f / lrow[mt][0], inv1 = 1.f / lrow[mt][1];
        #pragma unroll
        for (int nt = 0; nt < 8; nt++)
            #pragma unroll
            for (int r = 0; r < 4; r++) {
                int rl = w * 32 + mt * 16 + (lane >> 2) + (r >> 1) * 8;
                int d  = nt * 8 + (lane & 3) * 2 + (r & 1);
                float val = o[mt][nt][r] * ((r >> 1) ? inv1 : inv0);
                __half hi, lo; hilo(val, hi, lo);
                size_t idx = ((size_t)(b * 2048 + qb * 128 + rl)) * 2048 + h * 64 + d;
                Zc[idx] = hi;
                Zc[idx + 1024] = lo;
            }
    }
}

// ---------------------------------------------------------------------------
// Host launcher
// ---------------------------------------------------------------------------
extern "C" void kernel_launch(void* const* d_in, const int* in_sizes, int n_in,
                              void* d_out, int out_size)
{
    const float* query = (const float*)d_in[0];
    const float* key   = (const float*)d_in[1];
    const float* value = (const float*)d_in[2];
    const float* Wq = (const float*)d_in[3];  const float* bq = (const float*)d_in[4];
    const float* Wk = (const float*)d_in[5];  const float* bk = (const float*)d_in[6];
    const float* Wv = (const float*)d_in[7];  const float* bv = (const float*)d_in[8];
    const float* Wo = (const float*)d_in[9];  const float* bo = (const float*)d_in[10];

    __half *Qc, *Kc, *Vt, *Zc;
    cudaGetSymbolAddress((void**)&Qc, g_Qc);
    cudaGetSymbolAddress((void**)&Kc, g_Kc);
    cudaGetSymbolAddress((void**)&Vt, g_Vt);
    cudaGetSymbolAddress((void**)&Zc, g_Zc);

    cudaFuncSetAttribute(gemm_big<3>, cudaFuncAttributeMaxDynamicSharedMemorySize, GSMEM);
    cudaFuncSetAttribute(gemm_big<2>, cudaFuncAttributeMaxDynamicSharedMemorySize, GSMEM);
    cudaFuncSetAttribute(attn_mma, cudaFuncAttributeMaxDynamicSharedMemorySize, ATTN_SMEM);

    conv_w4<<<dim3(32, 32, 4), 256>>>(Wq, Wk, Wv, Wo);
    conv_x3<<<dim3(8192, 3), 256>>>(query, key, value);

    gemm_big<3><<<dim3(8, 128, 3), 128, GSMEM>>>(bq, bk, bv, nullptr);

    attn_mma<<<dim3(16, 64), 128, ATTN_SMEM>>>(Qc, Kc, Vt, Zc);

    gemm_big<2><<<dim3(8, 128, 1), 128, GSMEM>>>(bo, nullptr, nullptr, d_out);
}